// round 2
// baseline (speedup 1.0000x reference)
#include <cuda_runtime.h>

#define N_NODES 50000
#define N_EDGES 800000
#define FDIM 64

// ---------------- device scratch (static globals: allocation-free) ----------------
__device__ int   g_src[N_EDGES];
__device__ int   g_dst[N_EDGES];
__device__ int   g_csrc[N_EDGES];        // CSR: src ids grouped by dst
__device__ int   g_row[N_NODES + 1];     // CSR row offsets
__device__ int   g_cnt[N_NODES];         // in-degree histogram
__device__ int   g_cur[N_NODES];         // scatter cursors
__device__ __align__(16) float g_aggG[N_NODES * FDIM];  // GCN branch input (incl. self)
__device__ __align__(16) float g_aggA[N_NODES * FDIM];  // GAT branch input (normalized, incl. self)
__device__ __align__(16) float g_aggS[N_NODES * FDIM];  // plain neighbor sum (SAGE+GIN)
__device__ float g_ssrc[N_NODES];        // x . (W_gat @ a_src)
__device__ float g_sdst[N_NODES];        // x . (W_gat @ a_dst)
__device__ float g_dinv[N_NODES];        // rsqrt(deg + 1)

__device__ __forceinline__ float lrelu(float v) { return v > 0.f ? v : 0.2f * v; }

// ---------------- 0: zero histogram ----------------
__global__ void k_zero() {
    int i = blockIdx.x * blockDim.x + threadIdx.x;
    if (i < N_NODES) g_cnt[i] = 0;
}

// ---------------- 1: dtype-detect + convert + dst histogram ----------------
// int64 detection: ids < 50000 so all high 32-bit words are 0; if int32, the
// odd words are random ids (all-zero prob ~ (1/50000)^64 ~ 0).
__global__ void k_convert(const void* __restrict__ ei) {
    __shared__ int s_is64;
    const unsigned int* w = (const unsigned int*)ei;
    if (threadIdx.x == 0) {
        int z = 1;
        for (int i = 0; i < 64; i++) if (w[2 * i + 1] != 0u) { z = 0; break; }
        s_is64 = z;
    }
    __syncthreads();
    int is64 = s_is64;
    int stride = gridDim.x * blockDim.x;
    for (int i = blockIdx.x * blockDim.x + threadIdx.x; i < 2 * N_EDGES; i += stride) {
        int v;
        if (is64) v = (int)((const long long*)ei)[i];
        else      v = ((const int*)ei)[i];
        if (i < N_EDGES) g_src[i] = v;
        else {
            g_dst[i - N_EDGES] = v;
            atomicAdd(&g_cnt[v], 1);
        }
    }
}

// ---------------- 2: exclusive scan -> rowptr; dinv; zero cursors ----------------
#define SCAN_T 1024
#define SCAN_C 49   // 1024*49 = 50176 >= 50000
__global__ void k_scan() {
    __shared__ int ps[SCAN_T];
    int t = threadIdx.x;
    int base = t * SCAN_C;
    int sum = 0;
    #pragma unroll 4
    for (int i = 0; i < SCAN_C; i++) {
        int idx = base + i;
        if (idx < N_NODES) sum += g_cnt[idx];
    }
    ps[t] = sum;
    __syncthreads();
    // Hillis-Steele inclusive scan over 1024 partials
    for (int off = 1; off < SCAN_T; off <<= 1) {
        int v = (t >= off) ? ps[t - off] : 0;
        __syncthreads();
        ps[t] += v;
        __syncthreads();
    }
    int run = (t == 0) ? 0 : ps[t - 1];  // exclusive base
    #pragma unroll 4
    for (int i = 0; i < SCAN_C; i++) {
        int idx = base + i;
        if (idx < N_NODES) {
            int c = g_cnt[idx];
            g_row[idx] = run;
            g_cur[idx] = 0;
            g_dinv[idx] = rsqrtf((float)c + 1.0f);
            run += c;
        }
    }
    if (t == SCAN_T - 1) g_row[N_NODES] = run;
}

// ---------------- 3: per-node attention scalars (computes va/vb per block) ----------------
__global__ void k_node1(const float* __restrict__ x, const float* __restrict__ Wa,
                        const float* __restrict__ as_, const float* __restrict__ ad_) {
    __shared__ float sva[FDIM], svb[FDIM];
    if (threadIdx.x < FDIM) {
        int k = threadIdx.x;
        float va = 0.f, vb = 0.f;
        #pragma unroll 8
        for (int j = 0; j < FDIM; j++) {
            float wv = Wa[k * FDIM + j];
            va = fmaf(wv, as_[j], va);
            vb = fmaf(wv, ad_[j], vb);
        }
        sva[k] = va;
        svb[k] = vb;
    }
    __syncthreads();
    int n = blockIdx.x * blockDim.x + threadIdx.x;
    if (n >= N_NODES) return;
    const float4* xr = (const float4*)(x + (size_t)n * FDIM);
    float ss = 0.f, sd = 0.f;
    #pragma unroll
    for (int i = 0; i < FDIM / 4; i++) {
        float4 v = xr[i];
        ss = fmaf(v.x, sva[4*i], fmaf(v.y, sva[4*i+1], fmaf(v.z, sva[4*i+2], fmaf(v.w, sva[4*i+3], ss))));
        sd = fmaf(v.x, svb[4*i], fmaf(v.y, svb[4*i+1], fmaf(v.z, svb[4*i+2], fmaf(v.w, svb[4*i+3], sd))));
    }
    g_ssrc[n] = ss;
    g_sdst[n] = sd;
}

// ---------------- 4: scatter src into CSR ----------------
__global__ void k_scatter() {
    int stride = gridDim.x * blockDim.x;
    for (int e = blockIdx.x * blockDim.x + threadIdx.x; e < N_EDGES; e += stride) {
        int d = g_dst[e];
        int pos = g_row[d] + atomicAdd(&g_cur[d], 1);
        g_csrc[pos] = g_src[e];
    }
}

// ---------------- 5: warp-per-node aggregation (NO atomics) ----------------
__global__ void k_agg(const float* __restrict__ x) {
    int wid = blockIdx.x * (blockDim.x >> 5) + (threadIdx.x >> 5);
    int lane = threadIdx.x & 31;
    if (wid >= N_NODES) return;
    int d = wid;
    int row = g_row[d], end = g_row[d + 1];
    float sd = g_sdst[d];
    float dvd = g_dinv[d];

    // phase 1: softmax denominator (strided over edge list)
    float acc = 0.f;
    for (int e = row + lane; e < end; e += 32) {
        int s = g_csrc[e];
        acc += expf(lrelu(g_ssrc[s] + sd));
    }
    #pragma unroll
    for (int off = 16; off > 0; off >>= 1)
        acc += __shfl_xor_sync(0xffffffffu, acc, off);
    float selfexp = expf(lrelu(g_ssrc[d] + sd));
    float rdenom = 1.0f / (acc + selfexp);

    // phase 2: half-warp per edge; lane handles float4 segment q
    int q = lane & 15, half = lane >> 4;
    int deg = end - row;
    float4 aG = make_float4(0.f, 0.f, 0.f, 0.f);
    float4 aA = aG, aS = aG;
    for (int i = half; i < deg; i += 2) {
        int s = g_csrc[row + i];                       // broadcast within half-warp
        float wg = g_dinv[s] * dvd;
        float ae = expf(lrelu(g_ssrc[s] + sd));
        float4 xv = ((const float4*)x)[s * 16 + q];    // 256B coalesced per half-warp
        aG.x = fmaf(wg, xv.x, aG.x); aG.y = fmaf(wg, xv.y, aG.y);
        aG.z = fmaf(wg, xv.z, aG.z); aG.w = fmaf(wg, xv.w, aG.w);
        aA.x = fmaf(ae, xv.x, aA.x); aA.y = fmaf(ae, xv.y, aA.y);
        aA.z = fmaf(ae, xv.z, aA.z); aA.w = fmaf(ae, xv.w, aA.w);
        aS.x += xv.x; aS.y += xv.y; aS.z += xv.z; aS.w += xv.w;
    }
    // combine the two halves
    #pragma unroll
    for (int c = 0; c < 12; c++) {
        float* p = (c < 4) ? (&aG.x + c) : (c < 8) ? (&aA.x + (c - 4)) : (&aS.x + (c - 8));
        *p += __shfl_xor_sync(0xffffffffu, *p, 16);
    }
    if (half == 0) {
        float4 xd = ((const float4*)x)[d * 16 + q];
        float wd = dvd * dvd;
        float4 G = make_float4(fmaf(wd, xd.x, aG.x), fmaf(wd, xd.y, aG.y),
                               fmaf(wd, xd.z, aG.z), fmaf(wd, xd.w, aG.w));
        float4 A = make_float4((aA.x + selfexp * xd.x) * rdenom, (aA.y + selfexp * xd.y) * rdenom,
                               (aA.z + selfexp * xd.z) * rdenom, (aA.w + selfexp * xd.w) * rdenom);
        ((float4*)g_aggG)[d * 16 + q] = G;
        ((float4*)g_aggA)[d * 16 + q] = A;
        ((float4*)g_aggS)[d * 16 + q] = aS;
    }
}

// ---------------- 6: fused per-node head ----------------
#define NB 16
#define RR 4
#define SMEM_FLOATS (5*4096 + 256 + 256 + 5*NB*64 + NB + 2*NB)
#define SMEM_BYTES (SMEM_FLOATS * 4)

__global__ void k_final(const float* __restrict__ x,
                        const float* __restrict__ Wg, const float* __restrict__ bg,
                        const float* __restrict__ Wa, const float* __restrict__ ba,
                        const float* __restrict__ Wl, const float* __restrict__ bl,
                        const float* __restrict__ Wr,
                        const float* __restrict__ Wi, const float* __restrict__ bi,
                        const float* __restrict__ Wo, const float* __restrict__ bo,
                        float* __restrict__ out) {
    extern __shared__ float sm[];
    float* sW  = sm;                   // [5][64][64]: G, A, sage_l, sage_r, I
    float* sB  = sm + 5 * 4096;        // [4][64]
    float* sWo = sB + 256;             // [4][64]
    float* sIn = sWo + 256;            // [5][NB][64]
    float* sSc = sIn + 5 * NB * 64;    // [NB]: 1/max(deg,1)
    float* sRd = sSc + NB;             // [NB][2]
    int tid = threadIdx.x;

    for (int i = tid; i < 4096; i += 256) {
        sW[i]            = Wg[i];
        sW[4096 + i]     = Wa[i];
        sW[2 * 4096 + i] = Wl[i];
        sW[3 * 4096 + i] = Wr[i];
        sW[4 * 4096 + i] = Wi[i];
    }
    if (tid < 64) {
        sB[tid] = bg[tid]; sB[64 + tid] = ba[tid]; sB[128 + tid] = bl[tid]; sB[192 + tid] = bi[tid];
        sWo[tid] = Wo[tid]; sWo[64 + tid] = Wo[64 + tid];
        sWo[128 + tid] = Wo[128 + tid]; sWo[192 + tid] = Wo[192 + tid];
    }
    float bout = bo[0];
    __syncthreads();

    int j = tid & 63;
    int q = tid >> 6;
    float* sA1 = sIn;
    float* sA2 = sIn + NB * 64;
    float* sMn = sIn + 2 * NB * 64;
    float* sGi = sIn + 3 * NB * 64;
    float* sX  = sIn + 4 * NB * 64;

    for (int tile = blockIdx.x; tile < N_NODES / NB; tile += gridDim.x) {
        int base = tile * NB;
        if (tid < NB) {
            int n = base + tid;
            float deg = (float)(g_row[n + 1] - g_row[n]);
            sSc[tid] = 1.0f / fmaxf(deg, 1.0f);
        }
        __syncthreads();
        {
            int nl = tid >> 4, kq = tid & 15;
            int n = base + nl;
            float4 xv = ((const float4*)x)[n * 16 + kq];
            float4 ag = ((const float4*)g_aggG)[n * 16 + kq];
            float4 aa = ((const float4*)g_aggA)[n * 16 + kq];
            float4 as = ((const float4*)g_aggS)[n * 16 + kq];
            float ci = sSc[nl];
            int o = nl * 64 + kq * 4;
            *(float4*)&sA1[o] = ag;
            *(float4*)&sA2[o] = aa;
            *(float4*)&sMn[o] = make_float4(as.x * ci, as.y * ci, as.z * ci, as.w * ci);
            *(float4*)&sGi[o] = make_float4(xv.x + as.x, xv.y + as.y, xv.z + as.z, xv.w + as.w);
            *(float4*)&sX[o]  = xv;
        }
        __syncthreads();

        float accG[RR] = {0.f, 0.f, 0.f, 0.f};
        float accA[RR] = {0.f, 0.f, 0.f, 0.f};
        float accS[RR] = {0.f, 0.f, 0.f, 0.f};
        float accI[RR] = {0.f, 0.f, 0.f, 0.f};
        #pragma unroll 8
        for (int k = 0; k < 64; k++) {
            float wgc = sW[k * 64 + j];
            float wga = sW[4096 + k * 64 + j];
            float wsl = sW[2 * 4096 + k * 64 + j];
            float wsr = sW[3 * 4096 + k * 64 + j];
            float wgi = sW[4 * 4096 + k * 64 + j];
            #pragma unroll
            for (int r = 0; r < RR; r++) {
                int nl = q * RR + r;
                accG[r] = fmaf(sA1[nl * 64 + k], wgc, accG[r]);
                accA[r] = fmaf(sA2[nl * 64 + k], wga, accA[r]);
                accS[r] = fmaf(sMn[nl * 64 + k], wsl, accS[r]);
                accS[r] = fmaf(sX[nl * 64 + k],  wsr, accS[r]);
                accI[r] = fmaf(sGi[nl * 64 + k], wgi, accI[r]);
            }
        }
        #pragma unroll
        for (int r = 0; r < RR; r++) {
            float p = fmaxf(accG[r] + sB[j], 0.f) * sWo[j]
                    + fmaxf(accA[r] + sB[64 + j], 0.f) * sWo[64 + j]
                    + fmaxf(accS[r] + sB[128 + j], 0.f) * sWo[128 + j]
                    + fmaxf(accI[r] + sB[192 + j], 0.f) * sWo[192 + j];
            #pragma unroll
            for (int off = 16; off > 0; off >>= 1)
                p += __shfl_down_sync(0xffffffffu, p, off);
            if ((tid & 31) == 0)
                sRd[(q * RR + r) * 2 + ((j >> 5) & 1)] = p;
        }
        __syncthreads();
        if (tid < NB) {
            float z = sRd[tid * 2] + sRd[tid * 2 + 1] + bout;
            out[base + tid] = 1.0f / (1.0f + expf(-z));
        }
        __syncthreads();
    }
}

// ---------------- launch ----------------
extern "C" void kernel_launch(void* const* d_in, const int* in_sizes, int n_in,
                              void* d_out, int out_size) {
    const float* x    = (const float*)d_in[0];
    const void*  ei   = d_in[1];
    const float* Wg   = (const float*)d_in[2];
    const float* bg   = (const float*)d_in[3];
    const float* Wa   = (const float*)d_in[4];
    const float* asrc = (const float*)d_in[5];
    const float* adst = (const float*)d_in[6];
    const float* ba   = (const float*)d_in[7];
    const float* Wl   = (const float*)d_in[8];
    const float* bl   = (const float*)d_in[9];
    const float* Wr   = (const float*)d_in[10];
    const float* Wi   = (const float*)d_in[11];
    const float* bi   = (const float*)d_in[12];
    const float* Wo   = (const float*)d_in[13];
    const float* bo   = (const float*)d_in[14];
    float* out = (float*)d_out;

    cudaFuncSetAttribute(k_final, cudaFuncAttributeMaxDynamicSharedMemorySize, SMEM_BYTES);

    // launch index:                                             (ncu -s 5 -c 1 captures #5 = k_agg)
    k_zero<<<(N_NODES + 255) / 256, 256>>>();                          // 0
    k_convert<<<2048, 256>>>(ei);                                      // 1
    k_scan<<<1, SCAN_T>>>();                                           // 2
    k_node1<<<(N_NODES + 255) / 256, 256>>>(x, Wa, asrc, adst);        // 3
    k_scatter<<<1024, 256>>>();                                        // 4
    k_agg<<<(N_NODES + 7) / 8, 256>>>(x);                              // 5
    k_final<<<296, 256, SMEM_BYTES>>>(x, Wg, bg, Wa, ba, Wl, bl, Wr,   // 6
                                      Wi, bi, Wo, bo, out);
}

// round 3
// speedup vs baseline: 1.0379x; 1.0379x over previous
#include <cuda_runtime.h>

#define N_NODES 50000
#define N_EDGES 800000
#define FDIM 64

// ---------------- device scratch (static globals: allocation-free) ----------------
__device__ int   g_src[N_EDGES];
__device__ int   g_dst[N_EDGES];
__device__ int   g_csrc[N_EDGES];        // CSR: src ids grouped by dst
__device__ int   g_row[N_NODES + 1];     // CSR row offsets
__device__ int   g_cnt[N_NODES];         // in-degree histogram (memset to 0)
__device__ int   g_cur[N_NODES];         // scatter cursors
__device__ __align__(16) float g_aggG[N_NODES * FDIM];  // GCN branch input (incl. self)
__device__ __align__(16) float g_aggA[N_NODES * FDIM];  // GAT branch input (normalized, incl. self)
__device__ __align__(16) float g_aggS[N_NODES * FDIM];  // plain neighbor sum (SAGE+GIN)
__device__ float g_ssrc[N_NODES];        // x . (W_gat @ a_src)
__device__ float g_sdst[N_NODES];        // x . (W_gat @ a_dst)
__device__ float g_dinv[N_NODES];        // rsqrt(deg + 1)

__device__ __forceinline__ float lrelu(float v) { return v > 0.f ? v : 0.2f * v; }

// ---------------- 0: dtype-detect + convert + dst histogram ----------------
// int64 detection: ids < 50000 so all high 32-bit words are 0; if int32, the
// odd words are 64 random ids (all-zero prob ~ (1/50000)^64 ~ 0).
__global__ void k_convert(const void* __restrict__ ei) {
    __shared__ int s_is64;
    const unsigned int* w = (const unsigned int*)ei;
    if (threadIdx.x == 0) {
        int z = 1;
        for (int i = 0; i < 64; i++) if (w[2 * i + 1] != 0u) { z = 0; break; }
        s_is64 = z;
    }
    __syncthreads();
    int is64 = s_is64;
    int stride = gridDim.x * blockDim.x;
    for (int i = blockIdx.x * blockDim.x + threadIdx.x; i < 2 * N_EDGES; i += stride) {
        int v;
        if (is64) v = (int)((const long long*)ei)[i];
        else      v = ((const int*)ei)[i];
        if (i < N_EDGES) g_src[i] = v;
        else {
            g_dst[i - N_EDGES] = v;
            atomicAdd(&g_cnt[v], 1);
        }
    }
}

// ---------------- 1: exclusive scan -> rowptr; dinv; zero cursors ----------------
#define SCAN_T 1024
#define SCAN_C 49   // 1024*49 = 50176 >= 50000
__global__ void k_scan() {
    __shared__ int ps[SCAN_T];
    int t = threadIdx.x;
    int base = t * SCAN_C;
    int sum = 0;
    #pragma unroll 4
    for (int i = 0; i < SCAN_C; i++) {
        int idx = base + i;
        if (idx < N_NODES) sum += g_cnt[idx];
    }
    ps[t] = sum;
    __syncthreads();
    for (int off = 1; off < SCAN_T; off <<= 1) {
        int v = (t >= off) ? ps[t - off] : 0;
        __syncthreads();
        ps[t] += v;
        __syncthreads();
    }
    int run = (t == 0) ? 0 : ps[t - 1];  // exclusive base
    #pragma unroll 4
    for (int i = 0; i < SCAN_C; i++) {
        int idx = base + i;
        if (idx < N_NODES) {
            int c = g_cnt[idx];
            g_row[idx] = run;
            g_cur[idx] = 0;
            g_dinv[idx] = rsqrtf((float)c + 1.0f);
            run += c;
        }
    }
    if (t == SCAN_T - 1) g_row[N_NODES] = run;
}

// ---------------- 2: fused CSR scatter + per-node attention scalars ----------------
__global__ void k_scatter_node(const float* __restrict__ x, const float* __restrict__ Wa,
                               const float* __restrict__ as_, const float* __restrict__ ad_) {
    __shared__ float sva[FDIM], svb[FDIM];
    int gid = blockIdx.x * blockDim.x + threadIdx.x;

    // node part: only the first ceil(N/256) blocks
    if (blockIdx.x * blockDim.x < N_NODES) {
        if (threadIdx.x < FDIM) {
            int k = threadIdx.x;
            float va = 0.f, vb = 0.f;
            #pragma unroll 8
            for (int j = 0; j < FDIM; j++) {
                float wv = Wa[k * FDIM + j];
                va = fmaf(wv, as_[j], va);
                vb = fmaf(wv, ad_[j], vb);
            }
            sva[k] = va;
            svb[k] = vb;
        }
        __syncthreads();
        if (gid < N_NODES) {
            const float4* xr = (const float4*)(x + (size_t)gid * FDIM);
            float ss = 0.f, sd = 0.f;
            #pragma unroll
            for (int i = 0; i < FDIM / 4; i++) {
                float4 v = xr[i];
                ss = fmaf(v.x, sva[4*i], fmaf(v.y, sva[4*i+1], fmaf(v.z, sva[4*i+2], fmaf(v.w, sva[4*i+3], ss))));
                sd = fmaf(v.x, svb[4*i], fmaf(v.y, svb[4*i+1], fmaf(v.z, svb[4*i+2], fmaf(v.w, svb[4*i+3], sd))));
            }
            g_ssrc[gid] = ss;
            g_sdst[gid] = sd;
        }
    }

    // edge part: grid-stride CSR scatter
    int stride = gridDim.x * blockDim.x;
    for (int e = gid; e < N_EDGES; e += stride) {
        int d = g_dst[e];
        int pos = g_row[d] + atomicAdd(&g_cur[d], 1);
        g_csrc[pos] = g_src[e];
    }
}

// ---------------- 3: warp-per-node aggregation (no atomics, no redundant exp) ----------------
__global__ void __launch_bounds__(256) k_agg(const float* __restrict__ x) {
    int wid = (blockIdx.x * blockDim.x + threadIdx.x) >> 5;
    int lane = threadIdx.x & 31;
    if (wid >= N_NODES) return;
    int d = wid;
    int row = g_row[d], end = g_row[d + 1];
    float sd = g_sdst[d];
    float dvd = g_dinv[d];
    int q = lane & 15, half = lane >> 4;

    float4 aG = make_float4(0.f, 0.f, 0.f, 0.f);
    float4 aA = aG, aS = aG;
    float denom = 0.f;

    for (int base = row; base < end; base += 32) {
        int m = min(32, end - base);
        // phase A: one edge per lane — compute scalars exactly once per edge
        int   s_r = 0;
        float we_r = 0.f, wg_r = 0.f;
        if (lane < m) {
            s_r = g_csrc[base + lane];
            we_r = expf(lrelu(g_ssrc[s_r] + sd));
            wg_r = g_dinv[s_r] * dvd;
            denom += we_r;
        }
        // phase B: half-warp per edge; broadcast scalars via shuffle
        for (int i2 = 0; i2 < m; i2 += 2) {
            int i = i2 + half;
            int ic = (i < m) ? i : 0;
            int   s  = __shfl_sync(0xffffffffu, s_r, ic);
            float we = __shfl_sync(0xffffffffu, we_r, ic);
            float wg = __shfl_sync(0xffffffffu, wg_r, ic);
            if (i < m) {
                float4 xv = ((const float4*)x)[s * 16 + q];
                aG.x = fmaf(wg, xv.x, aG.x); aG.y = fmaf(wg, xv.y, aG.y);
                aG.z = fmaf(wg, xv.z, aG.z); aG.w = fmaf(wg, xv.w, aG.w);
                aA.x = fmaf(we, xv.x, aA.x); aA.y = fmaf(we, xv.y, aA.y);
                aA.z = fmaf(we, xv.z, aA.z); aA.w = fmaf(we, xv.w, aA.w);
                aS.x += xv.x; aS.y += xv.y; aS.z += xv.z; aS.w += xv.w;
            }
        }
    }

    // reduce denom across warp
    #pragma unroll
    for (int off = 16; off > 0; off >>= 1)
        denom += __shfl_xor_sync(0xffffffffu, denom, off);
    float selfexp = expf(lrelu(g_ssrc[d] + sd));
    float rdenom = 1.0f / (denom + selfexp);

    // combine the two halves
    #pragma unroll
    for (int c = 0; c < 12; c++) {
        float* p = (c < 4) ? (&aG.x + c) : (c < 8) ? (&aA.x + (c - 4)) : (&aS.x + (c - 8));
        *p += __shfl_xor_sync(0xffffffffu, *p, 16);
    }
    if (half == 0) {
        float4 xd = ((const float4*)x)[d * 16 + q];
        float wd = dvd * dvd;
        float4 G = make_float4(fmaf(wd, xd.x, aG.x), fmaf(wd, xd.y, aG.y),
                               fmaf(wd, xd.z, aG.z), fmaf(wd, xd.w, aG.w));
        float4 A = make_float4((aA.x + selfexp * xd.x) * rdenom, (aA.y + selfexp * xd.y) * rdenom,
                               (aA.z + selfexp * xd.z) * rdenom, (aA.w + selfexp * xd.w) * rdenom);
        ((float4*)g_aggG)[d * 16 + q] = G;
        ((float4*)g_aggA)[d * 16 + q] = A;
        ((float4*)g_aggS)[d * 16 + q] = aS;
    }
}

// ---------------- 4: fused per-node head ----------------
#define NB 16
#define RR 4
#define SMEM_FLOATS (5*4096 + 256 + 256 + 5*NB*64 + NB + 2*NB)
#define SMEM_BYTES (SMEM_FLOATS * 4)

__global__ void k_final(const float* __restrict__ x,
                        const float* __restrict__ Wg, const float* __restrict__ bg,
                        const float* __restrict__ Wa, const float* __restrict__ ba,
                        const float* __restrict__ Wl, const float* __restrict__ bl,
                        const float* __restrict__ Wr,
                        const float* __restrict__ Wi, const float* __restrict__ bi,
                        const float* __restrict__ Wo, const float* __restrict__ bo,
                        float* __restrict__ out) {
    extern __shared__ float sm[];
    float* sW  = sm;                   // [5][64][64]: G, A, sage_l, sage_r, I
    float* sB  = sm + 5 * 4096;        // [4][64]
    float* sWo = sB + 256;             // [4][64]
    float* sIn = sWo + 256;            // [5][NB][64]
    float* sSc = sIn + 5 * NB * 64;    // [NB]: 1/max(deg,1)
    float* sRd = sSc + NB;             // [NB][2]
    int tid = threadIdx.x;

    for (int i = tid; i < 4096; i += 256) {
        sW[i]            = Wg[i];
        sW[4096 + i]     = Wa[i];
        sW[2 * 4096 + i] = Wl[i];
        sW[3 * 4096 + i] = Wr[i];
        sW[4 * 4096 + i] = Wi[i];
    }
    if (tid < 64) {
        sB[tid] = bg[tid]; sB[64 + tid] = ba[tid]; sB[128 + tid] = bl[tid]; sB[192 + tid] = bi[tid];
        sWo[tid] = Wo[tid]; sWo[64 + tid] = Wo[64 + tid];
        sWo[128 + tid] = Wo[128 + tid]; sWo[192 + tid] = Wo[192 + tid];
    }
    float bout = bo[0];
    __syncthreads();

    int j = tid & 63;
    int q = tid >> 6;
    float* sA1 = sIn;
    float* sA2 = sIn + NB * 64;
    float* sMn = sIn + 2 * NB * 64;
    float* sGi = sIn + 3 * NB * 64;
    float* sX  = sIn + 4 * NB * 64;

    for (int tile = blockIdx.x; tile < N_NODES / NB; tile += gridDim.x) {
        int base = tile * NB;
        if (tid < NB) {
            int n = base + tid;
            float deg = (float)(g_row[n + 1] - g_row[n]);
            sSc[tid] = 1.0f / fmaxf(deg, 1.0f);
        }
        __syncthreads();
        {
            int nl = tid >> 4, kq = tid & 15;
            int n = base + nl;
            float4 xv = ((const float4*)x)[n * 16 + kq];
            float4 ag = ((const float4*)g_aggG)[n * 16 + kq];
            float4 aa = ((const float4*)g_aggA)[n * 16 + kq];
            float4 as = ((const float4*)g_aggS)[n * 16 + kq];
            float ci = sSc[nl];
            int o = nl * 64 + kq * 4;
            *(float4*)&sA1[o] = ag;
            *(float4*)&sA2[o] = aa;
            *(float4*)&sMn[o] = make_float4(as.x * ci, as.y * ci, as.z * ci, as.w * ci);
            *(float4*)&sGi[o] = make_float4(xv.x + as.x, xv.y + as.y, xv.z + as.z, xv.w + as.w);
            *(float4*)&sX[o]  = xv;
        }
        __syncthreads();

        float accG[RR] = {0.f, 0.f, 0.f, 0.f};
        float accA[RR] = {0.f, 0.f, 0.f, 0.f};
        float accS[RR] = {0.f, 0.f, 0.f, 0.f};
        float accI[RR] = {0.f, 0.f, 0.f, 0.f};
        #pragma unroll 8
        for (int k = 0; k < 64; k++) {
            float wgc = sW[k * 64 + j];
            float wga = sW[4096 + k * 64 + j];
            float wsl = sW[2 * 4096 + k * 64 + j];
            float wsr = sW[3 * 4096 + k * 64 + j];
            float wgi = sW[4 * 4096 + k * 64 + j];
            #pragma unroll
            for (int r = 0; r < RR; r++) {
                int nl = q * RR + r;
                accG[r] = fmaf(sA1[nl * 64 + k], wgc, accG[r]);
                accA[r] = fmaf(sA2[nl * 64 + k], wga, accA[r]);
                accS[r] = fmaf(sMn[nl * 64 + k], wsl, accS[r]);
                accS[r] = fmaf(sX[nl * 64 + k],  wsr, accS[r]);
                accI[r] = fmaf(sGi[nl * 64 + k], wgi, accI[r]);
            }
        }
        #pragma unroll
        for (int r = 0; r < RR; r++) {
            float p = fmaxf(accG[r] + sB[j], 0.f) * sWo[j]
                    + fmaxf(accA[r] + sB[64 + j], 0.f) * sWo[64 + j]
                    + fmaxf(accS[r] + sB[128 + j], 0.f) * sWo[128 + j]
                    + fmaxf(accI[r] + sB[192 + j], 0.f) * sWo[192 + j];
            #pragma unroll
            for (int off = 16; off > 0; off >>= 1)
                p += __shfl_down_sync(0xffffffffu, p, off);
            if ((tid & 31) == 0)
                sRd[(q * RR + r) * 2 + ((j >> 5) & 1)] = p;
        }
        __syncthreads();
        if (tid < NB) {
            float z = sRd[tid * 2] + sRd[tid * 2 + 1] + bout;
            out[base + tid] = 1.0f / (1.0f + expf(-z));
        }
        __syncthreads();
    }
}

// ---------------- launch ----------------
extern "C" void kernel_launch(void* const* d_in, const int* in_sizes, int n_in,
                              void* d_out, int out_size) {
    const float* x    = (const float*)d_in[0];
    const void*  ei   = d_in[1];
    const float* Wg   = (const float*)d_in[2];
    const float* bg   = (const float*)d_in[3];
    const float* Wa   = (const float*)d_in[4];
    const float* asrc = (const float*)d_in[5];
    const float* adst = (const float*)d_in[6];
    const float* ba   = (const float*)d_in[7];
    const float* Wl   = (const float*)d_in[8];
    const float* bl   = (const float*)d_in[9];
    const float* Wr   = (const float*)d_in[10];
    const float* Wi   = (const float*)d_in[11];
    const float* bi   = (const float*)d_in[12];
    const float* Wo   = (const float*)d_in[13];
    const float* bo   = (const float*)d_in[14];
    float* out = (float*)d_out;

    cudaFuncSetAttribute(k_final, cudaFuncAttributeMaxDynamicSharedMemorySize, SMEM_BYTES);

    void* cnt_ptr = nullptr;
    cudaGetSymbolAddress(&cnt_ptr, g_cnt);
    cudaMemsetAsync(cnt_ptr, 0, N_NODES * sizeof(int), 0);   // memset node, not a kernel

    // kernel launch index (ncu empirically profiles index 3 -> k_agg):
    k_convert<<<2048, 256>>>(ei);                                        // 0
    k_scan<<<1, SCAN_T>>>();                                             // 1
    k_scatter_node<<<3200, 256>>>(x, Wa, asrc, adst);                    // 2
    k_agg<<<(N_NODES * 32 + 255) / 256, 256>>>(x);                       // 3
    k_final<<<296, 256, SMEM_BYTES>>>(x, Wg, bg, Wa, ba, Wl, bl, Wr,     // 4
                                      Wi, bi, Wo, bo, out);
}

// round 5
// speedup vs baseline: 1.7624x; 1.6980x over previous
#include <cuda_runtime.h>

#define N_NODES 50000
#define N_EDGES 800000
#define FDIM 64
#define N_TILES ((N_NODES + 31) / 32)   // 1563

// ---------------- device scratch ----------------
__device__ int   g_src[N_EDGES];
__device__ int   g_dst[N_EDGES];
__device__ int   g_csrc[N_EDGES];          // CSR: src ids grouped by dst
__device__ int   g_row[N_NODES];           // CSR slice start per dst (arbitrary order)
__device__ int   g_cnt[N_NODES + 1];       // in-degree histogram; [N] = global offset counter
__device__ int   g_cur[N_NODES];           // scatter cursors
__device__ __align__(16) float g_aggG[N_NODES * FDIM];
__device__ __align__(16) float g_aggA[N_NODES * FDIM];
__device__ __align__(16) float g_aggS[N_NODES * FDIM];
__device__ float g_ssrc[N_NODES];
__device__ float g_sdst[N_NODES];
__device__ float g_dinv[N_NODES];

__device__ __forceinline__ float lrelu(float v) { return v > 0.f ? v : 0.2f * v; }

// ---------------- 0: dtype-detect + convert + histogram + per-node attn scalars ----------------
// int64 detection: ids < 50000 so high 32-bit words are 0; if int32, the odd
// words are 64 random ids (all-zero prob ~ (1/50000)^64 ~ 0).
__global__ void k_convert(const void* __restrict__ ei, const float* __restrict__ x,
                          const float* __restrict__ Wa, const float* __restrict__ as_,
                          const float* __restrict__ ad_) {
    __shared__ int s_is64;
    __shared__ float sva[FDIM], svb[FDIM];
    const unsigned int* w = (const unsigned int*)ei;
    int gid = blockIdx.x * blockDim.x + threadIdx.x;

    if (threadIdx.x == 0) {
        int z = 1;
        for (int i = 0; i < 64; i++) if (w[2 * i + 1] != 0u) { z = 0; break; }
        s_is64 = z;
    }
    // node part: first ceil(N/256) blocks compute ssrc/sdst (block-uniform branch)
    if (blockIdx.x * blockDim.x < N_NODES) {
        if (threadIdx.x < FDIM) {
            int k = threadIdx.x;
            float va = 0.f, vb = 0.f;
            #pragma unroll 8
            for (int j = 0; j < FDIM; j++) {
                float wv = Wa[k * FDIM + j];
                va = fmaf(wv, as_[j], va);
                vb = fmaf(wv, ad_[j], vb);
            }
            sva[k] = va;
            svb[k] = vb;
        }
        __syncthreads();
        if (gid < N_NODES) {
            const float4* xr = (const float4*)(x + (size_t)gid * FDIM);
            float ss = 0.f, sd = 0.f;
            #pragma unroll
            for (int i = 0; i < FDIM / 4; i++) {
                float4 v = xr[i];
                ss = fmaf(v.x, sva[4*i], fmaf(v.y, sva[4*i+1], fmaf(v.z, sva[4*i+2], fmaf(v.w, sva[4*i+3], ss))));
                sd = fmaf(v.x, svb[4*i], fmaf(v.y, svb[4*i+1], fmaf(v.z, svb[4*i+2], fmaf(v.w, svb[4*i+3], sd))));
            }
            g_ssrc[gid] = ss;
            g_sdst[gid] = sd;
        }
    } else {
        __syncthreads();
    }
    int is64 = s_is64;
    int stride = gridDim.x * blockDim.x;
    for (int i = gid; i < 2 * N_EDGES; i += stride) {
        int v;
        if (is64) v = (int)((const long long*)ei)[i];
        else      v = ((const int*)ei)[i];
        if (i < N_EDGES) g_src[i] = v;
        else {
            g_dst[i - N_EDGES] = v;
            atomicAdd(&g_cnt[v], 1);
        }
    }
}

// ---------------- 1: row-slice assignment (block scan + 1 atomic per block) ----------------
__global__ void k_rowassign() {
    __shared__ int s_warp[8];
    __shared__ int s_base;
    int tid = threadIdx.x;
    int n = blockIdx.x * 256 + tid;
    int lane = tid & 31, wid = tid >> 5;
    int c = (n < N_NODES) ? g_cnt[n] : 0;
    int v = c;
    #pragma unroll
    for (int off = 1; off < 32; off <<= 1) {
        int u = __shfl_up_sync(0xffffffffu, v, off);
        if (lane >= off) v += u;
    }
    if (lane == 31) s_warp[wid] = v;
    __syncthreads();
    if (tid < 8) {
        int pv = s_warp[tid];
        #pragma unroll
        for (int off = 1; off < 8; off <<= 1) {
            int u = __shfl_up_sync(0xffu, pv, off);
            if (tid >= off) pv += u;
        }
        s_warp[tid] = pv;
        if (tid == 7) s_base = atomicAdd(&g_cnt[N_NODES], pv);
    }
    __syncthreads();
    int excl = v - c + (wid > 0 ? s_warp[wid - 1] : 0);
    if (n < N_NODES) {
        g_row[n] = s_base + excl;
        g_cur[n] = 0;
        g_dinv[n] = rsqrtf((float)c + 1.0f);
    }
}

// ---------------- 2: scatter src into CSR ----------------
__global__ void k_scatter() {
    int stride = gridDim.x * blockDim.x;
    for (int e = blockIdx.x * blockDim.x + threadIdx.x; e < N_EDGES; e += stride) {
        int d = g_dst[e];
        int pos = g_row[d] + atomicAdd(&g_cur[d], 1);
        g_csrc[pos] = g_src[e];
    }
}

// ---------------- 3: warp-per-node aggregation (no atomics) ----------------
__global__ void __launch_bounds__(256) k_agg(const float* __restrict__ x) {
    int wid = (blockIdx.x * blockDim.x + threadIdx.x) >> 5;
    int lane = threadIdx.x & 31;
    if (wid >= N_NODES) return;
    int d = wid;
    int row = g_row[d], end = row + g_cnt[d];
    float sd = g_sdst[d];
    float dvd = g_dinv[d];
    int q = lane & 15, half = lane >> 4;

    float4 aG = make_float4(0.f, 0.f, 0.f, 0.f);
    float4 aA = aG, aS = aG;
    float denom = 0.f;

    for (int base = row; base < end; base += 32) {
        int m = min(32, end - base);
        int   s_r = 0;
        float we_r = 0.f, wg_r = 0.f;
        if (lane < m) {
            s_r = g_csrc[base + lane];
            we_r = expf(lrelu(g_ssrc[s_r] + sd));
            wg_r = g_dinv[s_r] * dvd;
            denom += we_r;
        }
        for (int i2 = 0; i2 < m; i2 += 2) {
            int i = i2 + half;
            int ic = (i < m) ? i : 0;
            int   s  = __shfl_sync(0xffffffffu, s_r, ic);
            float we = __shfl_sync(0xffffffffu, we_r, ic);
            float wg = __shfl_sync(0xffffffffu, wg_r, ic);
            if (i < m) {
                float4 xv = ((const float4*)x)[s * 16 + q];
                aG.x = fmaf(wg, xv.x, aG.x); aG.y = fmaf(wg, xv.y, aG.y);
                aG.z = fmaf(wg, xv.z, aG.z); aG.w = fmaf(wg, xv.w, aG.w);
                aA.x = fmaf(we, xv.x, aA.x); aA.y = fmaf(we, xv.y, aA.y);
                aA.z = fmaf(we, xv.z, aA.z); aA.w = fmaf(we, xv.w, aA.w);
                aS.x += xv.x; aS.y += xv.y; aS.z += xv.z; aS.w += xv.w;
            }
        }
    }

    #pragma unroll
    for (int off = 16; off > 0; off >>= 1)
        denom += __shfl_xor_sync(0xffffffffu, denom, off);
    float selfexp = expf(lrelu(g_ssrc[d] + sd));
    float rdenom = 1.0f / (denom + selfexp);

    #pragma unroll
    for (int c = 0; c < 12; c++) {
        float* p = (c < 4) ? (&aG.x + c) : (c < 8) ? (&aA.x + (c - 4)) : (&aS.x + (c - 8));
        *p += __shfl_xor_sync(0xffffffffu, *p, 16);
    }
    if (half == 0) {
        float4 xd = ((const float4*)x)[d * 16 + q];
        float wd = dvd * dvd;
        float4 G = make_float4(fmaf(wd, xd.x, aG.x), fmaf(wd, xd.y, aG.y),
                               fmaf(wd, xd.z, aG.z), fmaf(wd, xd.w, aG.w));
        float4 A = make_float4((aA.x + selfexp * xd.x) * rdenom, (aA.y + selfexp * xd.y) * rdenom,
                               (aA.z + selfexp * xd.z) * rdenom, (aA.w + selfexp * xd.w) * rdenom);
        ((float4*)g_aggG)[d * 16 + q] = G;
        ((float4*)g_aggA)[d * 16 + q] = A;
        ((float4*)g_aggS)[d * 16 + q] = aS;
    }
}

// ---------------- 4: register-blocked 6-panel GEMM + epilogue ----------------
// panels: 0: aggG@Wg  1: aggA@Wa  2: aggS@Wl  3: x@Wr  4: x@Wi  5: aggS@Wi
// smem float layout:
//   sW   [5][64][64]      @ 0        (20480)
//   sWo  [4][64]          @ 20480    (256)
//   sBias[4][64]          @ 20736    (256)
//   sU   [4][64][32]      @ 20992    (8192)   inputs transposed [k][node]
//   sP   [6][32][65]      @ 29184    (12480)  panel outputs, padded rows
//   sCi  [32]             @ 41664    (32)
#define KF_SMEM_FLOATS 41696
#define KF_SMEM_BYTES (KF_SMEM_FLOATS * 4)

__global__ void __launch_bounds__(384, 1) k_final(
        const float* __restrict__ x,
        const float* __restrict__ Wg, const float* __restrict__ bg,
        const float* __restrict__ Wa, const float* __restrict__ ba,
        const float* __restrict__ Wl, const float* __restrict__ bl,
        const float* __restrict__ Wr,
        const float* __restrict__ Wi, const float* __restrict__ bi,
        const float* __restrict__ Wo, const float* __restrict__ bo,
        float* __restrict__ out) {
    extern __shared__ float sm[];
    float* sW   = sm;
    float* sWo  = sm + 20480;
    float* sBia = sm + 20736;
    float* sU   = sm + 20992;
    float* sP   = sm + 29184;
    float* sCi  = sm + 41664;
    int tid = threadIdx.x;

    for (int i = tid; i < 4096; i += 384) {
        sW[i]            = Wg[i];
        sW[4096 + i]     = Wa[i];
        sW[2 * 4096 + i] = Wl[i];
        sW[3 * 4096 + i] = Wr[i];
        sW[4 * 4096 + i] = Wi[i];
    }
    if (tid < 256) sWo[tid] = Wo[tid];
    if (tid < 64) {
        sBia[tid] = bg[tid]; sBia[64 + tid] = ba[tid];
        sBia[128 + tid] = bl[tid]; sBia[192 + tid] = bi[tid];
    }
    float bout = bo[0];
    __syncthreads();

    int wwid = tid >> 5, lane = tid & 31;
    int p = wwid >> 1, ng = wwid & 1;
    int tx = lane & 15, ty = lane >> 4;
    int mtx = (p == 5) ? 4 : p;                              // weight matrix index
    int ain = (p == 0) ? 0 : (p == 1) ? 1 : (p == 2 || p == 5) ? 2 : 3;  // input array
    const float* Wp = sW + mtx * 4096;
    const float* Ub = sU + ain * 2048 + ng * 16 + ty * 8;

    const float4* gsrc[4] = { (const float4*)g_aggG, (const float4*)g_aggA,
                              (const float4*)g_aggS, (const float4*)x };

    for (int tile = blockIdx.x; tile < N_TILES; tile += gridDim.x) {
        int base = tile * 32;
        if (tid < 32) {
            int n = base + tid;
            sCi[tid] = (n < N_NODES) ? 1.0f / fmaxf((float)g_cnt[n], 1.0f) : 0.f;
        }
        // stage inputs transposed: 4 arrays x 32 nodes x 16 float4-chunks
        for (int idx = tid; idx < 2048; idx += 384) {
            int a2 = idx >> 9, rem = idx & 511;
            int nl = rem & 31, kq = rem >> 5;
            int n = base + nl;
            float4 v = make_float4(0.f, 0.f, 0.f, 0.f);
            if (n < N_NODES) v = gsrc[a2][n * 16 + kq];
            float* dstp = sU + a2 * 2048 + (kq * 4) * 32 + nl;
            dstp[0]  = v.x; dstp[32] = v.y; dstp[64] = v.z; dstp[96] = v.w;
        }
        __syncthreads();

        float acc[8][4];
        #pragma unroll
        for (int r = 0; r < 8; r++)
            #pragma unroll
            for (int jj = 0; jj < 4; jj++) acc[r][jj] = 0.f;

        #pragma unroll 4
        for (int k = 0; k < 64; k++) {
            float4 u0 = *(const float4*)(Ub + k * 32);
            float4 u1 = *(const float4*)(Ub + k * 32 + 4);
            float4 wv = *(const float4*)(Wp + k * 64 + tx * 4);
            float ur[8] = {u0.x, u0.y, u0.z, u0.w, u1.x, u1.y, u1.z, u1.w};
            #pragma unroll
            for (int r = 0; r < 8; r++) {
                acc[r][0] = fmaf(ur[r], wv.x, acc[r][0]);
                acc[r][1] = fmaf(ur[r], wv.y, acc[r][1]);
                acc[r][2] = fmaf(ur[r], wv.z, acc[r][2]);
                acc[r][3] = fmaf(ur[r], wv.w, acc[r][3]);
            }
        }
        #pragma unroll
        for (int r = 0; r < 8; r++) {
            int nl = ng * 16 + ty * 8 + r;
            float* pp = sP + (p * 32 + nl) * 65 + tx * 4;
            pp[0] = acc[r][0]; pp[1] = acc[r][1]; pp[2] = acc[r][2]; pp[3] = acc[r][3];
        }
        __syncthreads();

        if (tid < 256) {
            int nl = tid >> 3, jb = tid & 7;
            float ci = sCi[nl];
            float z = 0.f;
            #pragma unroll
            for (int jj = 0; jj < 8; jj++) {
                int j = jb * 8 + jj;
                float vg = sP[(0 * 32 + nl) * 65 + j] + sBia[j];
                float va2 = sP[(1 * 32 + nl) * 65 + j] + sBia[64 + j];
                float vs = fmaf(ci, sP[(2 * 32 + nl) * 65 + j], sP[(3 * 32 + nl) * 65 + j]) + sBia[128 + j];
                float vi = sP[(4 * 32 + nl) * 65 + j] + sP[(5 * 32 + nl) * 65 + j] + sBia[192 + j];
                z += fmaxf(vg, 0.f) * sWo[j] + fmaxf(va2, 0.f) * sWo[64 + j]
                   + fmaxf(vs, 0.f) * sWo[128 + j] + fmaxf(vi, 0.f) * sWo[192 + j];
            }
            z += __shfl_down_sync(0xffffffffu, z, 4);
            z += __shfl_down_sync(0xffffffffu, z, 2);
            z += __shfl_down_sync(0xffffffffu, z, 1);
            if ((tid & 7) == 0 && base + nl < N_NODES)
                out[base + nl] = 1.0f / (1.0f + expf(-(z + bout)));
        }
        __syncthreads();
    }
}

// ---------------- launch ----------------
extern "C" void kernel_launch(void* const* d_in, const int* in_sizes, int n_in,
                              void* d_out, int out_size) {
    const float* x    = (const float*)d_in[0];
    const void*  ei   = d_in[1];
    const float* Wg   = (const float*)d_in[2];
    const float* bg   = (const float*)d_in[3];
    const float* Wa   = (const float*)d_in[4];
    const float* asrc = (const float*)d_in[5];
    const float* adst = (const float*)d_in[6];
    const float* ba   = (const float*)d_in[7];
    const float* Wl   = (const float*)d_in[8];
    const float* bl   = (const float*)d_in[9];
    const float* Wr   = (const float*)d_in[10];
    const float* Wi   = (const float*)d_in[11];
    const float* bi   = (const float*)d_in[12];
    const float* Wo   = (const float*)d_in[13];
    const float* bo   = (const float*)d_in[14];
    float* out = (float*)d_out;

    cudaFuncSetAttribute(k_final, cudaFuncAttributeMaxDynamicSharedMemorySize, KF_SMEM_BYTES);

    void* cnt_ptr = nullptr;
    cudaGetSymbolAddress(&cnt_ptr, g_cnt);
    cudaMemsetAsync(cnt_ptr, 0, (N_NODES + 1) * sizeof(int), 0);

    k_convert<<<2048, 256>>>(ei, x, Wa, asrc, adst);                       // 0
    k_rowassign<<<(N_NODES + 255) / 256, 256>>>();                         // 1
    k_scatter<<<1024, 256>>>();                                            // 2
    k_agg<<<(N_NODES * 32 + 255) / 256, 256>>>(x);                         // 3 (profiled)
    k_final<<<148, 384, KF_SMEM_BYTES>>>(x, Wg, bg, Wa, ba, Wl, bl, Wr,    // 4
                                         Wi, bi, Wo, bo, out);
}